// round 1
// baseline (speedup 1.0000x reference)
#include <cuda_runtime.h>

// out[b] = ||x_b||^2 * (x_b^T rho x_b)
// X: [B, 256] f32, rho: [256, 256] f32, out: [B] f32

#define DIMX 256
#define ROWS_PER_BLOCK 32
#define NTHREADS 256

__global__ __launch_bounds__(NTHREADS, 2)
void qmd_kernel(const float* __restrict__ X,
                const float* __restrict__ rho,
                float* __restrict__ out, int B) {
    __shared__ float sx[ROWS_PER_BLOCK * DIMX];   // 32 KB X tile
    __shared__ float sq[2][ROWS_PER_BLOCK];
    __shared__ float sn[2][ROWS_PER_BLOCK];

    const int t  = threadIdx.x;
    const int b0 = blockIdx.x * ROWS_PER_BLOCK;

    // --- load X tile, vectorized (32*256 floats = 8 float4 per thread) ---
    const float4* __restrict__ Xg = reinterpret_cast<const float4*>(X + (size_t)b0 * DIMX);
    float4* sx4 = reinterpret_cast<float4*>(sx);
    #pragma unroll
    for (int i = 0; i < (ROWS_PER_BLOCK * DIMX / 4) / NTHREADS; i++)
        sx4[t + i * NTHREADS] = Xg[t + i * NTHREADS];
    __syncthreads();

    const int cg = t & 63;    // column group: rho cols 4*cg .. 4*cg+3
    const int rg = t >> 6;    // row group:   rows  rg*8 .. rg*8+7

    float acc[8][4];
    #pragma unroll
    for (int r = 0; r < 8; r++)
        #pragma unroll
        for (int j = 0; j < 4; j++) acc[r][j] = 0.0f;

    const float4* __restrict__ rho4 = reinterpret_cast<const float4*>(rho);
    const float* sxr = sx + rg * 8 * DIMX;

    // --- main loop: z[r][c] = sum_k x[r][k] * rho[k][c] ---
    #pragma unroll 4
    for (int k = 0; k < DIMX; k++) {
        const float4 rv = __ldg(&rho4[k * (DIMX / 4) + cg]);
        #pragma unroll
        for (int r = 0; r < 8; r++) {
            const float xv = sxr[r * DIMX + k];   // warp-uniform broadcast LDS
            acc[r][0] += xv * rv.x;
            acc[r][1] += xv * rv.y;
            acc[r][2] += xv * rv.z;
            acc[r][3] += xv * rv.w;
        }
    }

    // --- epilogue: q_part = dot(z, x) over this thread's 4 cols, n_part = ||x||^2 part ---
    float q[8], n[8];
    #pragma unroll
    for (int r = 0; r < 8; r++) {
        const float4 xv = *reinterpret_cast<const float4*>(&sxr[r * DIMX + 4 * cg]);
        q[r] = acc[r][0] * xv.x + acc[r][1] * xv.y + acc[r][2] * xv.z + acc[r][3] * xv.w;
        n[r] = xv.x * xv.x + xv.y * xv.y + xv.z * xv.z + xv.w * xv.w;
    }

    // warp reduction across 32 lanes (32 of the 64 column groups)
    #pragma unroll
    for (int off = 16; off > 0; off >>= 1) {
        #pragma unroll
        for (int r = 0; r < 8; r++) {
            q[r] += __shfl_xor_sync(0xffffffffu, q[r], off);
            n[r] += __shfl_xor_sync(0xffffffffu, n[r], off);
        }
    }

    const int lane = t & 31;
    const int w    = (t >> 5) & 1;   // which of the 2 warps in this row group
    if (lane == 0) {
        #pragma unroll
        for (int r = 0; r < 8; r++) {
            sq[w][rg * 8 + r] = q[r];
            sn[w][rg * 8 + r] = n[r];
        }
    }
    __syncthreads();

    if (t < ROWS_PER_BLOCK) {
        const float qq = sq[0][t] + sq[1][t];
        const float nn = sn[0][t] + sn[1][t];
        out[b0 + t] = nn * qq;
    }
}

extern "C" void kernel_launch(void* const* d_in, const int* in_sizes, int n_in,
                              void* d_out, int out_size) {
    const float* X   = (const float*)d_in[0];
    const float* rho = (const float*)d_in[1];
    float* out = (float*)d_out;
    const int B = out_size;                 // 4096 rows
    const int grid = B / ROWS_PER_BLOCK;    // 128 blocks
    qmd_kernel<<<grid, NTHREADS>>>(X, rho, out, B);
}

// round 4
// speedup vs baseline: 1.7590x; 1.7590x over previous
#include <cuda_runtime.h>
#include <cuda_bf16.h>
#include <cstdint>

// out[b] = ||x_b||^2 * (x_b^T rho x_b)
// Z = X @ rho^T via mma.sync m16n8k16 bf16 (portable ISA; tcgen05 rejected by
// harness's compute_103 virtual arch). Split: Z = Xh*Rh + Xh*Rl + Xl*Rh.

#define BATCH 4096
#define DIMX 256
#define TILE_M 32
#define NTHREADS 256
#define NKCHUNKS 4          // K chunks of 64

// bf16 hi/lo scratch (static device arrays: allowed, no allocation)
__device__ __nv_bfloat16 g_Xh[BATCH * DIMX];
__device__ __nv_bfloat16 g_Xl[BATCH * DIMX];
__device__ __nv_bfloat16 g_Rh[DIMX * DIMX];
__device__ __nv_bfloat16 g_Rl[DIMX * DIMX];

// ---- dynamic smem layout (bytes) ----
#define A_STRIDE 264        // bf16 elems per row (padded: 528B -> 4-bank row skew)
#define B_STRIDE 72         // bf16 elems per row (144B)
#define SM_AH    0                       // 32 x 264 bf16 = 16896
#define SM_AL    16896
#define SM_BH0   33792                   // 256 x 72 bf16 = 36864
#define SM_BL0   70656
#define SM_BH1   107520
#define SM_BL1   144384
#define SM_QP    181248                  // float[8][32]
#define SM_NP    182272
#define SMEM_TOTAL 183296

__device__ __forceinline__ uint32_t smem_u32(const void* p) {
    uint32_t a;
    asm("{ .reg .u64 t; cvta.to.shared.u64 t, %1; cvt.u32.u64 %0, t; }"
        : "=r"(a) : "l"(p));
    return a;
}
__device__ __forceinline__ void cp16(uint32_t dst, const void* src) {
    asm volatile("cp.async.cg.shared.global [%0], [%1], 16;" :: "r"(dst), "l"(src));
}
__device__ __forceinline__ void cp_commit() {
    asm volatile("cp.async.commit_group;" ::: "memory");
}
__device__ __forceinline__ void mma16816(float* c, const uint32_t* a, const uint32_t* b) {
    asm volatile(
        "mma.sync.aligned.m16n8k16.row.col.f32.bf16.bf16.f32 "
        "{%0,%1,%2,%3}, {%4,%5,%6,%7}, {%8,%9}, {%0,%1,%2,%3};"
        : "+f"(c[0]), "+f"(c[1]), "+f"(c[2]), "+f"(c[3])
        : "r"(a[0]), "r"(a[1]), "r"(a[2]), "r"(a[3]), "r"(b[0]), "r"(b[1]));
}
__device__ __forceinline__ void ldsm_x4(uint32_t* r, uint32_t addr) {
    asm volatile("ldmatrix.sync.aligned.m8n8.x4.shared.b16 {%0,%1,%2,%3}, [%4];"
                 : "=r"(r[0]), "=r"(r[1]), "=r"(r[2]), "=r"(r[3]) : "r"(addr));
}
__device__ __forceinline__ void ldsm_x2(uint32_t* r, uint32_t addr) {
    asm volatile("ldmatrix.sync.aligned.m8n8.x2.shared.b16 {%0,%1}, [%2];"
                 : "=r"(r[0]), "=r"(r[1]) : "r"(addr));
}

// ---------------- convert kernel: f32 -> (bf16 hi, bf16 lo) ----------------
__global__ void cvt_kernel(const float* __restrict__ X, const float* __restrict__ R) {
    const int NX = BATCH * DIMX / 4;     // float4 count for X
    const int NR = DIMX * DIMX / 4;
    int i = blockIdx.x * blockDim.x + threadIdx.x;
    if (i >= NX + NR) return;
    const float4* src;
    uint2 *dh, *dl;
    int idx;
    if (i < NX) {
        src = reinterpret_cast<const float4*>(X); idx = i;
        dh = reinterpret_cast<uint2*>(g_Xh); dl = reinterpret_cast<uint2*>(g_Xl);
    } else {
        src = reinterpret_cast<const float4*>(R); idx = i - NX;
        dh = reinterpret_cast<uint2*>(g_Rh); dl = reinterpret_cast<uint2*>(g_Rl);
    }
    float4 v = src[idx];
    __nv_bfloat162 h01 = __float22bfloat162_rn(make_float2(v.x, v.y));
    __nv_bfloat162 h23 = __float22bfloat162_rn(make_float2(v.z, v.w));
    float2 f01 = __bfloat1622float2(h01);
    float2 f23 = __bfloat1622float2(h23);
    __nv_bfloat162 l01 = __float22bfloat162_rn(make_float2(v.x - f01.x, v.y - f01.y));
    __nv_bfloat162 l23 = __float22bfloat162_rn(make_float2(v.z - f23.x, v.w - f23.y));
    uint2 hi, lo;
    hi.x = *reinterpret_cast<const uint32_t*>(&h01);
    hi.y = *reinterpret_cast<const uint32_t*>(&h23);
    lo.x = *reinterpret_cast<const uint32_t*>(&l01);
    lo.y = *reinterpret_cast<const uint32_t*>(&l23);
    dh[idx] = hi;
    dl[idx] = lo;
}

// ---------------- main fused GEMM + quadratic-form kernel ----------------
__global__ __launch_bounds__(NTHREADS, 1)
void qmd_mma(float* __restrict__ out) {
    extern __shared__ char smem[];
    const uint32_t sb = smem_u32(smem);
    const int t = threadIdx.x;
    const int wid = t >> 5;
    const int lane = t & 31;
    const int b0 = blockIdx.x * TILE_M;

    // ---- prefetch A tiles (hi+lo, full K) : 2048 x 16B / 256 thr = 8 each ----
    #pragma unroll
    for (int i = 0; i < 8; i++) {
        const int f = t + i * NTHREADS;
        const int arr = f >> 10, rem = f & 1023;
        const int r = rem >> 5, c = rem & 31;       // 32 x 32 (16B units)
        const uint32_t dst = sb + (arr ? SM_AL : SM_AH) + r * (A_STRIDE * 2) + c * 16;
        const __nv_bfloat16* src = (arr ? g_Xl : g_Xh) + (size_t)(b0 + r) * DIMX + c * 8;
        cp16(dst, src);
    }
    // ---- prefetch B chunk 0 then chunk 1 (double buffer) ----
    #pragma unroll
    for (int kb = 0; kb < 2; kb++) {
        const uint32_t bh = kb ? SM_BH1 : SM_BH0;
        const uint32_t bl = kb ? SM_BL1 : SM_BL0;
        #pragma unroll
        for (int i = 0; i < 16; i++) {
            const int f = t + i * NTHREADS;         // 0..4095
            const int arr = f >> 11, rem = f & 2047;
            const int n = rem >> 3, c = rem & 7;    // 256 rows x 8 (16B units)
            const uint32_t dst = sb + (arr ? bl : bh) + n * (B_STRIDE * 2) + c * 16;
            const __nv_bfloat16* src = (arr ? g_Rl : g_Rh) + (size_t)n * DIMX + kb * 64 + c * 8;
            cp16(dst, src);
        }
        cp_commit();
    }

    float acc[2][4][4];
    #pragma unroll
    for (int mi = 0; mi < 2; mi++)
        #pragma unroll
        for (int ni = 0; ni < 4; ni++)
            #pragma unroll
            for (int e = 0; e < 4; e++) acc[mi][ni][e] = 0.0f;

    const int n_base = wid * 32;

    for (int kb = 0; kb < NKCHUNKS; kb++) {
        if (kb == NKCHUNKS - 1)
            asm volatile("cp.async.wait_group 0;" ::: "memory");
        else
            asm volatile("cp.async.wait_group 1;" ::: "memory");
        __syncthreads();

        const uint32_t bh = (kb & 1) ? SM_BH1 : SM_BH0;
        const uint32_t bl = (kb & 1) ? SM_BL1 : SM_BL0;

        #pragma unroll
        for (int k16 = 0; k16 < 4; k16++) {
            const int kcA = kb * 64 + k16 * 16;     // A global col
            const int kcB = k16 * 16;               // B chunk-local col

            // A fragments (hi, lo): ldmatrix x4 per m16 block
            uint32_t aH[2][4], aL[2][4];
            {
                const int m_idx = lane >> 3;
                const int arow = (m_idx & 1) * 8 + (lane & 7);
                const int acol = kcA + (m_idx >> 1) * 8;
                #pragma unroll
                for (int mi = 0; mi < 2; mi++) {
                    const uint32_t ao = (mi * 16 + arow) * (A_STRIDE * 2) + acol * 2;
                    ldsm_x4(aH[mi], sb + SM_AH + ao);
                    ldsm_x4(aL[mi], sb + SM_AL + ao);
                }
            }
            // B fragments (hi, lo): ldmatrix x2 per n8 block
            uint32_t bH[4][2], bL[4][2];
            {
                const int l2 = lane & 15;
                const int m_idx = l2 >> 3;
                const int brow = l2 & 7;
                const int bcol = kcB + m_idx * 8;
                #pragma unroll
                for (int ni = 0; ni < 4; ni++) {
                    const uint32_t bo = (n_base + ni * 8 + brow) * (B_STRIDE * 2) + bcol * 2;
                    ldsm_x2(bH[ni], sb + bh + bo);
                    ldsm_x2(bL[ni], sb + bl + bo);
                }
            }
            // 3-term MMAs
            #pragma unroll
            for (int mi = 0; mi < 2; mi++)
                #pragma unroll
                for (int ni = 0; ni < 4; ni++) {
                    mma16816(acc[mi][ni], aH[mi], bH[ni]);
                    mma16816(acc[mi][ni], aH[mi], bL[ni]);
                    mma16816(acc[mi][ni], aL[mi], bH[ni]);
                }
        }
        __syncthreads();

        // prefetch chunk kb+2 into the buffer just consumed
        if (kb < NKCHUNKS - 2) {
            const int nk = kb + 2;
            #pragma unroll
            for (int i = 0; i < 16; i++) {
                const int f = t + i * NTHREADS;
                const int arr = f >> 11, rem = f & 2047;
                const int n = rem >> 3, c = rem & 7;
                const uint32_t dst = sb + (arr ? bl : bh) + n * (B_STRIDE * 2) + c * 16;
                const __nv_bfloat16* src = (arr ? g_Rl : g_Rh) + (size_t)n * DIMX + nk * 64 + c * 8;
                cp16(dst, src);
            }
            cp_commit();
        }
    }

    // ---- fused epilogue: q_r = sum_j Z[r,j]*x[r,j],  n_r = sum_j x[r,j]^2 ----
    const __nv_bfloat16* sAh = reinterpret_cast<const __nv_bfloat16*>(smem + SM_AH);
    const __nv_bfloat16* sAl = reinterpret_cast<const __nv_bfloat16*>(smem + SM_AL);
    float q[4] = {0, 0, 0, 0};
    float nn[4] = {0, 0, 0, 0};
    #pragma unroll
    for (int mi = 0; mi < 2; mi++) {
        #pragma unroll
        for (int ni = 0; ni < 4; ni++) {
            const int j0 = n_base + ni * 8 + (lane & 3) * 2;
            const int r0 = mi * 16 + (lane >> 2);
            #pragma unroll
            for (int e = 0; e < 4; e++) {
                const int r = r0 + (e >> 1) * 8;
                const int j = j0 + (e & 1);
                const float xf = __bfloat162float(sAh[r * A_STRIDE + j]) +
                                 __bfloat162float(sAl[r * A_STRIDE + j]);
                const int slot = mi * 2 + (e >> 1);   // row = lane/4 + slot*8
                q[slot] = fmaf(acc[mi][ni][e], xf, q[slot]);
                nn[slot] = fmaf(xf, xf, nn[slot]);
            }
        }
    }
    // quad reduction (lanes sharing the same row group)
    #pragma unroll
    for (int off = 1; off <= 2; off <<= 1) {
        #pragma unroll
        for (int s = 0; s < 4; s++) {
            q[s] += __shfl_xor_sync(0xffffffffu, q[s], off);
            nn[s] += __shfl_xor_sync(0xffffffffu, nn[s], off);
        }
    }
    float* qp = reinterpret_cast<float*>(smem + SM_QP);
    float* np = reinterpret_cast<float*>(smem + SM_NP);
    if ((lane & 3) == 0) {
        #pragma unroll
        for (int s = 0; s < 4; s++) {
            const int r = (lane >> 2) + s * 8;
            qp[wid * 32 + r] = q[s];
            np[wid * 32 + r] = nn[s];
        }
    }
    __syncthreads();

    if (t < TILE_M) {
        float qq = 0.0f, ns = 0.0f;
        #pragma unroll
        for (int w = 0; w < 8; w++) {
            qq += qp[w * 32 + t];
            ns += np[w * 32 + t];
        }
        out[b0 + t] = qq * ns;
    }
}

extern "C" void kernel_launch(void* const* d_in, const int* in_sizes, int n_in,
                              void* d_out, int out_size) {
    const float* X   = (const float*)d_in[0];
    const float* rho = (const float*)d_in[1];
    float* out = (float*)d_out;

    const int NCVT = (BATCH * DIMX + DIMX * DIMX) / 4;
    cvt_kernel<<<(NCVT + 255) / 256, 256>>>(X, rho);

    cudaFuncSetAttribute(qmd_mma, cudaFuncAttributeMaxDynamicSharedMemorySize, SMEM_TOTAL);
    qmd_mma<<<out_size / TILE_M, NTHREADS, SMEM_TOTAL>>>(out);
}

// round 5
// speedup vs baseline: 1.8489x; 1.0511x over previous
#include <cuda_runtime.h>
#include <cuda_bf16.h>
#include <cstdint>

// out[b] = ||x_b||^2 * (x_b^T rho x_b)
// Z = X @ rho^T via mma.sync m16n8k16 bf16. Split: Z = Xh*Rh + Xh*Rl + Xl*Rh.
// R5: 512 threads/CTA (16 warps) for latency hiding; X conversion fused into
// main kernel (cvt kernel converts rho only).

#define BATCH 4096
#define DIMX 256
#define TILE_M 32
#define NTHREADS 512
#define NKCHUNKS 4          // K chunks of 64

// bf16 hi/lo scratch for rho (static device arrays: no allocation)
__device__ __nv_bfloat16 g_Rh[DIMX * DIMX];
__device__ __nv_bfloat16 g_Rl[DIMX * DIMX];

// ---- dynamic smem layout (bytes) ----
#define A_STRIDE 264        // bf16 elems per row (528B row pitch)
#define B_STRIDE 72         // bf16 elems per row (144B)
#define SM_AH    0                       // 32 x 264 bf16 = 16896
#define SM_AL    16896
#define SM_BH0   33792                   // 256 x 72 bf16 = 36864
#define SM_BL0   70656
#define SM_BH1   107520
#define SM_BL1   144384
#define SM_QP    181248                  // float[16][32] = 2048
#define SM_NP    183296                  // float[16][32] = 2048
#define SMEM_TOTAL 185344

__device__ __forceinline__ uint32_t smem_u32(const void* p) {
    uint32_t a;
    asm("{ .reg .u64 t; cvta.to.shared.u64 t, %1; cvt.u32.u64 %0, t; }"
        : "=r"(a) : "l"(p));
    return a;
}
__device__ __forceinline__ void cp16(uint32_t dst, const void* src) {
    asm volatile("cp.async.cg.shared.global [%0], [%1], 16;" :: "r"(dst), "l"(src));
}
__device__ __forceinline__ void cp_commit() {
    asm volatile("cp.async.commit_group;" ::: "memory");
}
__device__ __forceinline__ void mma16816(float* c, const uint32_t* a, const uint32_t* b) {
    asm volatile(
        "mma.sync.aligned.m16n8k16.row.col.f32.bf16.bf16.f32 "
        "{%0,%1,%2,%3}, {%4,%5,%6,%7}, {%8,%9}, {%0,%1,%2,%3};"
        : "+f"(c[0]), "+f"(c[1]), "+f"(c[2]), "+f"(c[3])
        : "r"(a[0]), "r"(a[1]), "r"(a[2]), "r"(a[3]), "r"(b[0]), "r"(b[1]));
}
__device__ __forceinline__ void ldsm_x4(uint32_t* r, uint32_t addr) {
    asm volatile("ldmatrix.sync.aligned.m8n8.x4.shared.b16 {%0,%1,%2,%3}, [%4];"
                 : "=r"(r[0]), "=r"(r[1]), "=r"(r[2]), "=r"(r[3]) : "r"(addr));
}
__device__ __forceinline__ void ldsm_x2(uint32_t* r, uint32_t addr) {
    asm volatile("ldmatrix.sync.aligned.m8n8.x2.shared.b16 {%0,%1}, [%2];"
                 : "=r"(r[0]), "=r"(r[1]) : "r"(addr));
}
__device__ __forceinline__ void split4(const float4 v, uint2& hi, uint2& lo) {
    __nv_bfloat162 h01 = __float22bfloat162_rn(make_float2(v.x, v.y));
    __nv_bfloat162 h23 = __float22bfloat162_rn(make_float2(v.z, v.w));
    float2 f01 = __bfloat1622float2(h01);
    float2 f23 = __bfloat1622float2(h23);
    __nv_bfloat162 l01 = __float22bfloat162_rn(make_float2(v.x - f01.x, v.y - f01.y));
    __nv_bfloat162 l23 = __float22bfloat162_rn(make_float2(v.z - f23.x, v.w - f23.y));
    hi.x = *reinterpret_cast<const uint32_t*>(&h01);
    hi.y = *reinterpret_cast<const uint32_t*>(&h23);
    lo.x = *reinterpret_cast<const uint32_t*>(&l01);
    lo.y = *reinterpret_cast<const uint32_t*>(&l23);
}

// ---------------- rho convert kernel: f32 -> (bf16 hi, bf16 lo) ----------------
__global__ void cvt_rho(const float* __restrict__ R) {
    const int NR = DIMX * DIMX / 4;
    int i = blockIdx.x * blockDim.x + threadIdx.x;
    if (i >= NR) return;
    float4 v = reinterpret_cast<const float4*>(R)[i];
    uint2 hi, lo;
    split4(v, hi, lo);
    reinterpret_cast<uint2*>(g_Rh)[i] = hi;
    reinterpret_cast<uint2*>(g_Rl)[i] = lo;
}

// ---------------- main fused GEMM + quadratic-form kernel ----------------
__global__ __launch_bounds__(NTHREADS, 1)
void qmd_mma(const float* __restrict__ X, float* __restrict__ out) {
    extern __shared__ char smem[];
    const uint32_t sb = smem_u32(smem);
    const int t = threadIdx.x;
    const int wid = t >> 5;
    const int lane = t & 31;
    const int b0 = blockIdx.x * TILE_M;

    // ---- prefetch B chunk 0 and 1 via cp.async (double buffer) ----
    #pragma unroll
    for (int kb = 0; kb < 2; kb++) {
        const uint32_t bh = kb ? SM_BH1 : SM_BH0;
        const uint32_t bl = kb ? SM_BL1 : SM_BL0;
        #pragma unroll
        for (int i = 0; i < 8; i++) {
            const int f = t + i * NTHREADS;         // 0..4095
            const int arr = f >> 11, rem = f & 2047;
            const int n = rem >> 3, c = rem & 7;    // 256 rows x 8 (16B units)
            const uint32_t dst = sb + (arr ? bl : bh) + n * (B_STRIDE * 2) + c * 16;
            const __nv_bfloat16* src = (arr ? g_Rl : g_Rh) + (size_t)n * DIMX + kb * 64 + c * 8;
            cp16(dst, src);
        }
        cp_commit();
    }

    // ---- load + convert A tile (X f32 -> bf16 hi/lo in smem), overlaps cp.async ----
    {
        const float4* __restrict__ Xg = reinterpret_cast<const float4*>(X);
        #pragma unroll
        for (int i = 0; i < 4; i++) {
            const int f = t + i * NTHREADS;         // 0..2047
            const int r = f >> 6, c4 = f & 63;      // 32 rows x 64 float4
            float4 v = Xg[(size_t)(b0 + r) * (DIMX / 4) + c4];
            uint2 hi, lo;
            split4(v, hi, lo);
            const uint32_t off = r * (A_STRIDE * 2) + c4 * 8;
            *reinterpret_cast<uint2*>(smem + SM_AH + off) = hi;
            *reinterpret_cast<uint2*>(smem + SM_AL + off) = lo;
        }
    }

    float acc[2][2][4];
    #pragma unroll
    for (int mi = 0; mi < 2; mi++)
        #pragma unroll
        for (int ni = 0; ni < 2; ni++)
            #pragma unroll
            for (int e = 0; e < 4; e++) acc[mi][ni][e] = 0.0f;

    const int n_base = wid * 16;

    for (int kb = 0; kb < NKCHUNKS; kb++) {
        if (kb == NKCHUNKS - 1)
            asm volatile("cp.async.wait_group 0;" ::: "memory");
        else
            asm volatile("cp.async.wait_group 1;" ::: "memory");
        __syncthreads();

        const uint32_t bh = (kb & 1) ? SM_BH1 : SM_BH0;
        const uint32_t bl = (kb & 1) ? SM_BL1 : SM_BL0;

        #pragma unroll
        for (int k16 = 0; k16 < 4; k16++) {
            const int kcA = kb * 64 + k16 * 16;     // A global col
            const int kcB = k16 * 16;               // B chunk-local col

            // A fragments (hi, lo): ldmatrix x4 per m16 block
            uint32_t aH[2][4], aL[2][4];
            {
                const int m_idx = lane >> 3;
                const int arow = (m_idx & 1) * 8 + (lane & 7);
                const int acol = kcA + (m_idx >> 1) * 8;
                #pragma unroll
                for (int mi = 0; mi < 2; mi++) {
                    const uint32_t ao = (mi * 16 + arow) * (A_STRIDE * 2) + acol * 2;
                    ldsm_x4(aH[mi], sb + SM_AH + ao);
                    ldsm_x4(aL[mi], sb + SM_AL + ao);
                }
            }
            // B fragments (hi, lo): ldmatrix x2 per n8 block
            uint32_t bH[2][2], bL[2][2];
            {
                const int l2 = lane & 15;
                const int m_idx = l2 >> 3;
                const int brow = l2 & 7;
                const int bcol = kcB + m_idx * 8;
                #pragma unroll
                for (int ni = 0; ni < 2; ni++) {
                    const uint32_t bo = (n_base + ni * 8 + brow) * (B_STRIDE * 2) + bcol * 2;
                    ldsm_x2(bH[ni], sb + bh + bo);
                    ldsm_x2(bL[ni], sb + bl + bo);
                }
            }
            // 3-term MMAs
            #pragma unroll
            for (int mi = 0; mi < 2; mi++)
                #pragma unroll
                for (int ni = 0; ni < 2; ni++) {
                    mma16816(acc[mi][ni], aH[mi], bH[ni]);
                    mma16816(acc[mi][ni], aH[mi], bL[ni]);
                    mma16816(acc[mi][ni], aL[mi], bH[ni]);
                }
        }
        __syncthreads();

        // prefetch chunk kb+2 into the buffer just consumed
        if (kb < NKCHUNKS - 2) {
            const int nk = kb + 2;
            #pragma unroll
            for (int i = 0; i < 8; i++) {
                const int f = t + i * NTHREADS;
                const int arr = f >> 11, rem = f & 2047;
                const int n = rem >> 3, c = rem & 7;
                const uint32_t dst = sb + (arr ? bl : bh) + n * (B_STRIDE * 2) + c * 16;
                const __nv_bfloat16* src = (arr ? g_Rl : g_Rh) + (size_t)n * DIMX + nk * 64 + c * 8;
                cp16(dst, src);
            }
            cp_commit();
        }
    }

    // ---- fused epilogue: q_r = sum_j Z[r,j]*x[r,j],  n_r = sum_j x[r,j]^2 ----
    const __nv_bfloat16* sAh = reinterpret_cast<const __nv_bfloat16*>(smem + SM_AH);
    const __nv_bfloat16* sAl = reinterpret_cast<const __nv_bfloat16*>(smem + SM_AL);
    float q[4] = {0, 0, 0, 0};
    float nn[4] = {0, 0, 0, 0};
    #pragma unroll
    for (int mi = 0; mi < 2; mi++) {
        #pragma unroll
        for (int ni = 0; ni < 2; ni++) {
            const int j0 = n_base + ni * 8 + (lane & 3) * 2;
            const int r0 = mi * 16 + (lane >> 2);
            #pragma unroll
            for (int e = 0; e < 4; e++) {
                const int r = r0 + (e >> 1) * 8;
                const int j = j0 + (e & 1);
                const float xf = __bfloat162float(sAh[r * A_STRIDE + j]) +
                                 __bfloat162float(sAl[r * A_STRIDE + j]);
                const int slot = mi * 2 + (e >> 1);   // row = lane>>2 + slot*8
                q[slot] = fmaf(acc[mi][ni][e], xf, q[slot]);
                nn[slot] = fmaf(xf, xf, nn[slot]);
            }
        }
    }
    // quad reduction (lanes sharing the same rows)
    #pragma unroll
    for (int off = 1; off <= 2; off <<= 1) {
        #pragma unroll
        for (int s = 0; s < 4; s++) {
            q[s] += __shfl_xor_sync(0xffffffffu, q[s], off);
            nn[s] += __shfl_xor_sync(0xffffffffu, nn[s], off);
        }
    }
    float* qp = reinterpret_cast<float*>(smem + SM_QP);
    float* np = reinterpret_cast<float*>(smem + SM_NP);
    if ((lane & 3) == 0) {
        #pragma unroll
        for (int s = 0; s < 4; s++) {
            const int r = (lane >> 2) + s * 8;
            qp[wid * 32 + r] = q[s];
            np[wid * 32 + r] = nn[s];
        }
    }
    __syncthreads();

    if (t < TILE_M) {
        float qq = 0.0f, ns = 0.0f;
        #pragma unroll
        for (int w = 0; w < 16; w++) {
            qq += qp[w * 32 + t];
            ns += np[w * 32 + t];
        }
        out[b0 + t] = qq * ns;
    }
}

extern "C" void kernel_launch(void* const* d_in, const int* in_sizes, int n_in,
                              void* d_out, int out_size) {
    const float* X   = (const float*)d_in[0];
    const float* rho = (const float*)d_in[1];
    float* out = (float*)d_out;

    const int NR4 = DIMX * DIMX / 4;
    cvt_rho<<<(NR4 + 255) / 256, 256>>>(rho);

    cudaFuncSetAttribute(qmd_mma, cudaFuncAttributeMaxDynamicSharedMemorySize, SMEM_TOTAL);
    qmd_mma<<<out_size / TILE_M, NTHREADS, SMEM_TOTAL>>>(X, out);
}